// round 1
// baseline (speedup 1.0000x reference)
#include <cuda_runtime.h>
#include <math.h>

// Problem constants
constexpr int NL    = 4;      // layers
constexpr int DIM   = 512;    // model dim
constexpr int NH    = 8;      // heads
constexpr int HD    = 64;     // head dim
constexpr int DFFN  = 2048;   // ffn dim
constexpr int SEQ   = 512;    // sequence length
constexpr int BATCH = 16;     // batch
constexpr int NCLS  = 3;      // classes
constexpr int MR    = BATCH * SEQ;  // 8192 rows

// ---------------- scratch (device globals: allocation-free) ----------------
__device__ float g_x  [MR * DIM];
__device__ float g_h  [MR * DIM];
__device__ float g_q  [MR * DIM];
__device__ float g_k  [MR * DIM];
__device__ float g_v  [MR * DIM];
__device__ float g_ctx[MR * DIM];
__device__ float g_ffn[MR * DFFN];
__device__ float g_la [MR * NCLS];
__device__ float g_lb [MR * NCLS];

// ---------------- embedding + sinusoidal PE ----------------
// x[b,n,d] = emb_table[src[n,b]] * sqrt(D) + pe[n,d]
__global__ void embed_kernel(const int* __restrict__ src,
                             const float* __restrict__ emb) {
    int idx = blockIdx.x * blockDim.x + threadIdx.x;
    if (idx >= MR * DIM) return;
    int d = idx % DIM;
    int m = idx / DIM;
    int b = m / SEQ;
    int n = m % SEQ;
    int tok = src[n * BATCH + b];
    float e = emb[(size_t)tok * DIM + d] * 22.62741699796952f; // sqrt(512)
    int i2 = (d >> 1) * 2;
    float freq = expf((float)i2 * (-9.210340371976184f / (float)DIM)); // -ln(10000)/D
    float ang = (float)n * freq;
    float pe = (d & 1) ? cosf(ang) : sinf(ang);
    g_x[idx] = e + pe;
}

// ---------------- LayerNorm: one block per row, 128 threads ----------------
__global__ void ln_kernel(const float* __restrict__ in, float* __restrict__ out,
                          const float* __restrict__ gg, const float* __restrict__ bb) {
    int row = blockIdx.x;
    int t = threadIdx.x;
    const float* p = in + (size_t)row * DIM;
    float v[4];
    float s = 0.f, ss = 0.f;
#pragma unroll
    for (int i = 0; i < 4; i++) {
        float x = p[t + i * 128];
        v[i] = x; s += x; ss += x * x;
    }
#pragma unroll
    for (int off = 16; off >= 1; off >>= 1) {
        s  += __shfl_xor_sync(0xffffffffu, s, off);
        ss += __shfl_xor_sync(0xffffffffu, ss, off);
    }
    __shared__ float rs[4], rss[4];
    int w = t >> 5, lane = t & 31;
    if (lane == 0) { rs[w] = s; rss[w] = ss; }
    __syncthreads();
    float S  = rs[0] + rs[1] + rs[2] + rs[3];
    float SS = rss[0] + rss[1] + rss[2] + rss[3];
    float mean = S * (1.f / DIM);
    float var  = SS * (1.f / DIM) - mean * mean;
    float rstd = rsqrtf(var + 1e-6f);
    float* o = out + (size_t)row * DIM;
#pragma unroll
    for (int i = 0; i < 4; i++) {
        int c = t + i * 128;
        o[c] = (v[i] - mean) * rstd * gg[c] + bb[c];
    }
}

// ---------------- SGEMM: C[M,Nc] = A[M,K] @ W[K,Nc] (+bias, epilogues) -----
// EPI: 0 = bias, 1 = bias + residual, 2 = bias + relu
// QKV: 1 = scatter output to [B,H,N,HD] layout
template<int EPI, int QKV>
__global__ __launch_bounds__(256, 2)
void sgemm(const float* __restrict__ A, const float* __restrict__ W,
           const float* __restrict__ bias, const float* __restrict__ resid,
           float* __restrict__ Cout, int K, int Nc) {
    __shared__ float As[8][128];
    __shared__ float Bs[8][128];
    const int tid = threadIdx.x;
    const int tx = tid & 15;
    const int ty = tid >> 4;
    const int row0 = blockIdx.y * 128;
    const int col0 = blockIdx.x * 128;
    const int arow = tid >> 1;
    const int acol = (tid & 1) << 2;
    const int wrow = tid >> 5;
    const int wcol = (tid & 31) << 2;
    float acc[8][8];
#pragma unroll
    for (int i = 0; i < 8; i++)
#pragma unroll
        for (int j = 0; j < 8; j++) acc[i][j] = 0.f;

    const float* Aptr = A + (size_t)(row0 + arow) * K + acol;
    const float* Wptr = W + (size_t)wrow * Nc + col0 + wcol;

    for (int k0 = 0; k0 < K; k0 += 8) {
        float4 a4 = *(const float4*)(Aptr + k0);
        float4 b4 = *(const float4*)(Wptr + (size_t)k0 * Nc);
        As[acol + 0][arow] = a4.x;
        As[acol + 1][arow] = a4.y;
        As[acol + 2][arow] = a4.z;
        As[acol + 3][arow] = a4.w;
        *(float4*)&Bs[wrow][wcol] = b4;
        __syncthreads();
#pragma unroll
        for (int kk = 0; kk < 8; kk++) {
            float ra[8], rb[8];
            *(float4*)(ra)     = *(const float4*)&As[kk][ty * 8];
            *(float4*)(ra + 4) = *(const float4*)&As[kk][ty * 8 + 4];
            *(float4*)(rb)     = *(const float4*)&Bs[kk][tx * 8];
            *(float4*)(rb + 4) = *(const float4*)&Bs[kk][tx * 8 + 4];
#pragma unroll
            for (int i = 0; i < 8; i++)
#pragma unroll
                for (int j = 0; j < 8; j++)
                    acc[i][j] += ra[i] * rb[j];
        }
        __syncthreads();
    }

#pragma unroll
    for (int i = 0; i < 8; i++) {
        int r = row0 + ty * 8 + i;
#pragma unroll
        for (int j = 0; j < 8; j++) {
            int c = col0 + tx * 8 + j;
            float val = acc[i][j] + bias[c];
            if (EPI == 1) val += resid[(size_t)r * Nc + c];
            if (EPI == 2) val = fmaxf(val, 0.f);
            if (QKV) {
                int b = r >> 9, n = r & 511, hh = c >> 6, dd = c & 63;
                Cout[(((size_t)(b * NH + hh)) * SEQ + n) * HD + dd] = val;
            } else {
                Cout[(size_t)r * Nc + c] = val;
            }
        }
    }
}

// ---------------- attention: streaming softmax, 8 q rows / CTA ------------
// q/k/v in [B,H,N,HD]; ctx written back in [B,N,D]
__global__ void attn_kernel(const int* __restrict__ lengths) {
    constexpr int QR = 8;
    int blk = blockIdx.x;                   // B*NH*SEQ/QR = 8192
    int qt = blk % (SEQ / QR);
    int bh = blk / (SEQ / QR);
    int b = bh / NH, hh = bh % NH;
    int t = threadIdx.x;                    // 64 threads (= HD)
    int w = t >> 5, lane = t & 31;

    __shared__ float k_sm[64][65];
    __shared__ float v_sm[64][65];
    __shared__ float q_sm[QR][64];
    __shared__ float p_sm[QR][64];
    __shared__ float red_max[16];
    __shared__ float red_sum[16];

    const float* Qp = g_q + ((size_t)bh * SEQ + qt * QR) * HD;
#pragma unroll
    for (int r = 0; r < QR; r++) q_sm[r][t] = Qp[r * HD + t] * 0.125f; // /sqrt(64)

    float m[QR], l[QR], acc[QR];
#pragma unroll
    for (int r = 0; r < QR; r++) { m[r] = -1e30f; l[r] = 0.f; acc[r] = 0.f; }
    int len = lengths[b];

    const float* Kp = g_k + (size_t)bh * SEQ * HD;
    const float* Vp = g_v + (size_t)bh * SEQ * HD;

    for (int kt = 0; kt < SEQ; kt += 64) {
        __syncthreads();
#pragma unroll 4
        for (int rr = 0; rr < 64; rr++) {
            k_sm[rr][t] = Kp[(kt + rr) * HD + t];
            v_sm[rr][t] = Vp[(kt + rr) * HD + t];
        }
        __syncthreads();

        float s[QR];
#pragma unroll
        for (int r = 0; r < QR; r++) s[r] = 0.f;
#pragma unroll 8
        for (int d = 0; d < 64; d++) {
            float kv = k_sm[t][d];
#pragma unroll
            for (int r = 0; r < QR; r++) s[r] += q_sm[r][d] * kv;
        }
        if (kt + t >= len) {
#pragma unroll
            for (int r = 0; r < QR; r++) s[r] = -1e9f;
        }

        // per-row block max via warp shuffle + 2-warp combine
#pragma unroll
        for (int r = 0; r < QR; r++) {
            float vm = s[r];
#pragma unroll
            for (int off = 16; off >= 1; off >>= 1)
                vm = fmaxf(vm, __shfl_xor_sync(0xffffffffu, vm, off));
            if (lane == 0) red_max[w * QR + r] = vm;
        }
        __syncthreads();

        float corr[QR];
#pragma unroll
        for (int r = 0; r < QR; r++) {
            float tmax = fmaxf(red_max[r], red_max[QR + r]);
            float mn = fmaxf(m[r], tmax);
            corr[r] = expf(m[r] - mn);
            m[r] = mn;
            float p = expf(s[r] - mn);
            p_sm[r][t] = p;
            float ps = p;
#pragma unroll
            for (int off = 16; off >= 1; off >>= 1)
                ps += __shfl_xor_sync(0xffffffffu, ps, off);
            if (lane == 0) red_sum[w * QR + r] = ps;
        }
        __syncthreads();

#pragma unroll
        for (int r = 0; r < QR; r++) {
            l[r] = l[r] * corr[r] + red_sum[r] + red_sum[QR + r];
            acc[r] *= corr[r];
        }
#pragma unroll 8
        for (int kk = 0; kk < 64; kk++) {
            float vv = v_sm[kk][t];
#pragma unroll
            for (int r = 0; r < QR; r++) acc[r] += p_sm[r][kk] * vv;
        }
    }

#pragma unroll
    for (int r = 0; r < QR; r++) {
        int qi = qt * QR + r;
        g_ctx[((size_t)b * SEQ + qi) * DIM + hh * HD + t] = acc[r] / l[r];
    }
}

// ---------------- attn_res output: [N,B,D] transpose of final LN ----------
__global__ void out1_kernel(float* __restrict__ out1) {
    int idx = blockIdx.x * blockDim.x + threadIdx.x;
    if (idx >= MR * DIM) return;
    int d = idx % DIM;
    int nb = idx / DIM;
    int b = nb % BATCH;
    int n = nb / BATCH;
    out1[idx] = g_h[((size_t)b * SEQ + n) * DIM + d];
}

// ---------------- la/lb = xf @ inf_W[:D] / inf_W[D:]  (C=3) ---------------
__global__ void infw_kernel(const float* __restrict__ W) {
    int mrow = blockIdx.x;     // MR
    int t = threadIdx.x;       // 64
    float a[NCLS] = {0, 0, 0}, bv2[NCLS] = {0, 0, 0};
    const float* xp = g_h + (size_t)mrow * DIM;
    for (int d = t; d < DIM; d += 64) {
        float xv = xp[d];
#pragma unroll
        for (int c = 0; c < NCLS; c++) {
            a[c]   += xv * W[(size_t)d * NCLS + c];
            bv2[c] += xv * W[(size_t)(DIM + d) * NCLS + c];
        }
    }
    __shared__ float red[6][64];
#pragma unroll
    for (int c = 0; c < NCLS; c++) { red[c][t] = a[c]; red[3 + c][t] = bv2[c]; }
    __syncthreads();
    for (int sft = 32; sft >= 1; sft >>= 1) {
        if (t < sft) {
#pragma unroll
            for (int c = 0; c < 6; c++) red[c][t] += red[c][t + sft];
        }
        __syncthreads();
    }
    if (t == 0) {
#pragma unroll
        for (int c = 0; c < NCLS; c++) {
            g_la[mrow * NCLS + c] = red[c][0];
            g_lb[mrow * NCLS + c] = red[3 + c][0];
        }
    }
}

// ---------------- pairwise logits + log_softmax -> out [(i*N+j)*B+b]*3+c --
__global__ void pair_kernel(float* __restrict__ out2) {
    int idx = blockIdx.x * blockDim.x + threadIdx.x;
    if (idx >= SEQ * SEQ * BATCH) return;
    int b = idx % BATCH;
    int j = (idx / BATCH) % SEQ;
    int i = idx / (BATCH * SEQ);
    const float* lap = g_la + ((size_t)b * SEQ + i) * NCLS;
    const float* lbp = g_lb + ((size_t)b * SEQ + j) * NCLS;
    float v0 = lap[0] + lbp[0];
    float v1 = lap[1] + lbp[1];
    float v2 = lap[2] + lbp[2];
    float mx = fmaxf(v0, fmaxf(v1, v2));
    float lse = mx + logf(expf(v0 - mx) + expf(v1 - mx) + expf(v2 - mx));
    float* o = out2 + (size_t)idx * NCLS;
    o[0] = v0 - lse; o[1] = v1 - lse; o[2] = v2 - lse;
}

// ---------------- orchestration ----------------
extern "C" void kernel_launch(void* const* d_in, const int* in_sizes, int n_in,
                              void* d_out, int out_size) {
    (void)in_sizes; (void)n_in; (void)out_size;
    const int*   src     = (const int*)  d_in[0];
    const int*   lengths = (const int*)  d_in[1];
    const float* emb     = (const float*)d_in[2];
    const float* ln1_g   = (const float*)d_in[3];
    const float* ln1_b   = (const float*)d_in[4];
    const float* Wq      = (const float*)d_in[5];
    const float* bq      = (const float*)d_in[6];
    const float* Wk      = (const float*)d_in[7];
    const float* bk      = (const float*)d_in[8];
    const float* Wv      = (const float*)d_in[9];
    const float* bv      = (const float*)d_in[10];
    const float* Wo      = (const float*)d_in[11];
    const float* bo      = (const float*)d_in[12];
    const float* ln2_g   = (const float*)d_in[13];
    const float* ln2_b   = (const float*)d_in[14];
    const float* W1      = (const float*)d_in[15];
    const float* b1      = (const float*)d_in[16];
    const float* W2      = (const float*)d_in[17];
    const float* b2      = (const float*)d_in[18];
    const float* lnf_g   = (const float*)d_in[19];
    const float* lnf_b   = (const float*)d_in[20];
    const float* inf_W   = (const float*)d_in[21];
    float* out = (float*)d_out;

    float *px, *ph, *pq, *pk, *pv, *pctx, *pffn;
    cudaGetSymbolAddress((void**)&px,   g_x);
    cudaGetSymbolAddress((void**)&ph,   g_h);
    cudaGetSymbolAddress((void**)&pq,   g_q);
    cudaGetSymbolAddress((void**)&pk,   g_k);
    cudaGetSymbolAddress((void**)&pv,   g_v);
    cudaGetSymbolAddress((void**)&pctx, g_ctx);
    cudaGetSymbolAddress((void**)&pffn, g_ffn);

    embed_kernel<<<(MR * DIM + 255) / 256, 256>>>(src, emb);

    for (int l = 0; l < NL; l++) {
        const float* wq = Wq + (size_t)l * DIM * DIM;
        const float* wk = Wk + (size_t)l * DIM * DIM;
        const float* wv = Wv + (size_t)l * DIM * DIM;
        const float* wo = Wo + (size_t)l * DIM * DIM;
        const float* w1 = W1 + (size_t)l * DIM * DFFN;
        const float* w2 = W2 + (size_t)l * DFFN * DIM;

        ln_kernel<<<MR, 128>>>(px, ph, ln1_g + l * DIM, ln1_b + l * DIM);

        dim3 gD(DIM / 128, MR / 128);    // (4, 64)
        sgemm<0, 1><<<gD, 256>>>(ph, wq, bq + l * DIM, nullptr, pq, DIM, DIM);
        sgemm<0, 1><<<gD, 256>>>(ph, wk, bk + l * DIM, nullptr, pk, DIM, DIM);
        sgemm<0, 1><<<gD, 256>>>(ph, wv, bv + l * DIM, nullptr, pv, DIM, DIM);

        attn_kernel<<<BATCH * NH * SEQ / 8, 64>>>(lengths);

        sgemm<1, 0><<<gD, 256>>>(pctx, wo, bo + l * DIM, px, px, DIM, DIM);

        ln_kernel<<<MR, 128>>>(px, ph, ln2_g + l * DIM, ln2_b + l * DIM);

        dim3 gF(DFFN / 128, MR / 128);   // (16, 64)
        sgemm<2, 0><<<gF, 256>>>(ph, w1, b1 + l * DFFN, nullptr, pffn, DIM, DFFN);
        sgemm<1, 0><<<gD, 256>>>(pffn, w2, b2 + l * DIM, px, px, DFFN, DIM);
    }

    ln_kernel<<<MR, 128>>>(px, ph, lnf_g, lnf_b);

    out1_kernel<<<(MR * DIM + 255) / 256, 256>>>(out);
    infw_kernel<<<MR, 64>>>(inf_W);
    pair_kernel<<<(SEQ * SEQ * BATCH + 255) / 256, 256>>>(out + (size_t)MR * DIM);
}

// round 2
// speedup vs baseline: 1.9032x; 1.9032x over previous
#include <cuda_runtime.h>
#include <math.h>

// Problem constants
constexpr int NL    = 4;
constexpr int DIM   = 512;
constexpr int NH    = 8;
constexpr int HD    = 64;
constexpr int DFFN  = 2048;
constexpr int SEQ   = 512;
constexpr int BATCH = 16;
constexpr int NCLS  = 3;
constexpr int MR    = BATCH * SEQ;  // 8192

// ---------------- scratch ----------------
__device__ float g_x  [MR * DIM];
__device__ float g_h  [MR * DIM];
__device__ float g_q  [MR * DIM];
__device__ float g_k  [MR * DIM];
__device__ float g_v  [MR * DIM];
__device__ float g_ctx[MR * DIM];
__device__ float g_ffn[MR * DFFN];
__device__ float g_la [MR * NCLS];
__device__ float g_lb [MR * NCLS];

// ---------------- embedding + PE ----------------
__global__ void embed_kernel(const int* __restrict__ src,
                             const float* __restrict__ emb) {
    int idx = blockIdx.x * blockDim.x + threadIdx.x;
    if (idx >= MR * DIM) return;
    int d = idx % DIM;
    int m = idx / DIM;
    int b = m / SEQ;
    int n = m % SEQ;
    int tok = src[n * BATCH + b];
    float e = emb[(size_t)tok * DIM + d] * 22.62741699796952f;
    int i2 = (d >> 1) * 2;
    float freq = expf((float)i2 * (-9.210340371976184f / (float)DIM));
    float ang = (float)n * freq;
    float pe = (d & 1) ? cosf(ang) : sinf(ang);
    g_x[idx] = e + pe;
}

// ---------------- LayerNorm ----------------
__global__ void ln_kernel(const float* __restrict__ in, float* __restrict__ out,
                          const float* __restrict__ gg, const float* __restrict__ bb) {
    int row = blockIdx.x;
    int t = threadIdx.x;
    const float* p = in + (size_t)row * DIM;
    float v[4];
    float s = 0.f, ss = 0.f;
#pragma unroll
    for (int i = 0; i < 4; i++) {
        float x = p[t + i * 128];
        v[i] = x; s += x; ss += x * x;
    }
#pragma unroll
    for (int off = 16; off >= 1; off >>= 1) {
        s  += __shfl_xor_sync(0xffffffffu, s, off);
        ss += __shfl_xor_sync(0xffffffffu, ss, off);
    }
    __shared__ float rs[4], rss[4];
    int w = t >> 5, lane = t & 31;
    if (lane == 0) { rs[w] = s; rss[w] = ss; }
    __syncthreads();
    float S  = rs[0] + rs[1] + rs[2] + rs[3];
    float SS = rss[0] + rss[1] + rss[2] + rss[3];
    float mean = S * (1.f / DIM);
    float var  = SS * (1.f / DIM) - mean * mean;
    float rstd = rsqrtf(var + 1e-6f);
    float* o = out + (size_t)row * DIM;
#pragma unroll
    for (int i = 0; i < 4; i++) {
        int c = t + i * 128;
        o[c] = (v[i] - mean) * rstd * gg[c] + bb[c];
    }
}

// ---------------- tf32 helpers ----------------
__device__ __forceinline__ unsigned f2tf(float x) {
    unsigned r;
    asm("cvt.rna.tf32.f32 %0, %1;" : "=r"(r) : "f"(x));
    return r;
}

__device__ __forceinline__ void mma_tf32(float c[4], const unsigned a[4], const unsigned b[2]) {
    asm volatile(
        "mma.sync.aligned.m16n8k8.row.col.f32.tf32.tf32.f32 "
        "{%0,%1,%2,%3}, {%4,%5,%6,%7}, {%8,%9}, {%0,%1,%2,%3};"
        : "+f"(c[0]), "+f"(c[1]), "+f"(c[2]), "+f"(c[3])
        : "r"(a[0]), "r"(a[1]), "r"(a[2]), "r"(a[3]),
          "r"(b[0]), "r"(b[1]));
}

// ---------------- tensor-core GEMM (tf32 mma.sync) ----------------
// C[M,Nc] = A[M,K] @ W[K,Nc], row-major.
// BM=128, BN=128, BK=16, 256 threads (8 warps, 2m x 4n of 64x32 warp tiles).
// EPI: 0 = bias, 1 = bias + residual, 2 = bias + relu
// QKV: 1 = scatter output to [B,H,N,HD]
template<int EPI, int QKV>
__global__ __launch_bounds__(256, 2)
void tgemm(const float* __restrict__ A, const float* __restrict__ W,
           const float* __restrict__ bias, const float* __restrict__ resid,
           float* __restrict__ Cout, int K, int Nc) {
    constexpr int BK = 16;
    constexpr int LD = 136;  // padded (8-float skew -> conflict-free frag loads)
    __shared__ float As[2][BK][LD];  // As[k][m] = A[row0+m][kb+k] (tf32 bits)
    __shared__ float Bs[2][BK][LD];  // Bs[k][n] = W[kb+k][col0+n] (tf32 bits)

    const int tid  = threadIdx.x;
    const int w    = tid >> 5;
    const int lane = tid & 31;
    const int g    = lane >> 2;     // 0..7
    const int tq   = lane & 3;      // 0..3
    const int wrow = (w & 1) * 64;
    const int wcol = (w >> 1) * 32;
    const int row0 = blockIdx.y * 128;
    const int col0 = blockIdx.x * 128;

    // global load indices
    const int arow = tid >> 1;            // 0..127
    const int acol = (tid & 1) * 8;       // 0 or 8
    const int brow = tid >> 4;            // 0..15
    const int bcol = (tid & 15) * 8;      // 0..120

    const float* Ap = A + (size_t)(row0 + arow) * K + acol;
    const float* Wp = W + (size_t)brow * Nc + col0 + bcol;

    float C[4][4][4];
#pragma unroll
    for (int i = 0; i < 4; i++)
#pragma unroll
        for (int j = 0; j < 4; j++)
#pragma unroll
            for (int q = 0; q < 4; q++) C[i][j][q] = 0.f;

    const int nblk = K / BK;

    // preload block 0
    float4 ra0 = *(const float4*)(Ap);
    float4 ra1 = *(const float4*)(Ap + 4);
    float4 rb0 = *(const float4*)(Wp);
    float4 rb1 = *(const float4*)(Wp + 4);

    {
        float* as = &As[0][acol][arow];
        as[0 * LD] = __uint_as_float(f2tf(ra0.x));
        as[1 * LD] = __uint_as_float(f2tf(ra0.y));
        as[2 * LD] = __uint_as_float(f2tf(ra0.z));
        as[3 * LD] = __uint_as_float(f2tf(ra0.w));
        as[4 * LD] = __uint_as_float(f2tf(ra1.x));
        as[5 * LD] = __uint_as_float(f2tf(ra1.y));
        as[6 * LD] = __uint_as_float(f2tf(ra1.z));
        as[7 * LD] = __uint_as_float(f2tf(ra1.w));
        float4 c0 = make_float4(__uint_as_float(f2tf(rb0.x)), __uint_as_float(f2tf(rb0.y)),
                                __uint_as_float(f2tf(rb0.z)), __uint_as_float(f2tf(rb0.w)));
        float4 c1 = make_float4(__uint_as_float(f2tf(rb1.x)), __uint_as_float(f2tf(rb1.y)),
                                __uint_as_float(f2tf(rb1.z)), __uint_as_float(f2tf(rb1.w)));
        *(float4*)&Bs[0][brow][bcol]     = c0;
        *(float4*)&Bs[0][brow][bcol + 4] = c1;
    }
    __syncthreads();

    int s = 0;
    for (int blk = 0; blk < nblk; blk++) {
        // prefetch next block into registers
        float4 na0, na1, nb0, nb1;
        if (blk + 1 < nblk) {
            const float* ap = Ap + (blk + 1) * BK;
            const float* wp = Wp + (size_t)(blk + 1) * BK * Nc;
            na0 = *(const float4*)(ap);
            na1 = *(const float4*)(ap + 4);
            nb0 = *(const float4*)(wp);
            nb1 = *(const float4*)(wp + 4);
        }

        // compute current stage: 2 k-steps of 8
#pragma unroll
        for (int ks = 0; ks < 2; ks++) {
            const int kb = ks * 8;
            unsigned af[4][4], bf[4][2];
#pragma unroll
            for (int mt = 0; mt < 4; mt++) {
                int r = wrow + mt * 16 + g;
                af[mt][0] = __float_as_uint(As[s][kb + tq][r]);
                af[mt][1] = __float_as_uint(As[s][kb + tq][r + 8]);
                af[mt][2] = __float_as_uint(As[s][kb + tq + 4][r]);
                af[mt][3] = __float_as_uint(As[s][kb + tq + 4][r + 8]);
            }
#pragma unroll
            for (int nt = 0; nt < 4; nt++) {
                int c = wcol + nt * 8 + g;
                bf[nt][0] = __float_as_uint(Bs[s][kb + tq][c]);
                bf[nt][1] = __float_as_uint(Bs[s][kb + tq + 4][c]);
            }
#pragma unroll
            for (int mt = 0; mt < 4; mt++)
#pragma unroll
                for (int nt = 0; nt < 4; nt++)
                    mma_tf32(C[mt][nt], af[mt], bf[nt]);
        }

        if (blk + 1 < nblk) {
            int ns = s ^ 1;
            float* as = &As[ns][acol][arow];
            as[0 * LD] = __uint_as_float(f2tf(na0.x));
            as[1 * LD] = __uint_as_float(f2tf(na0.y));
            as[2 * LD] = __uint_as_float(f2tf(na0.z));
            as[3 * LD] = __uint_as_float(f2tf(na0.w));
            as[4 * LD] = __uint_as_float(f2tf(na1.x));
            as[5 * LD] = __uint_as_float(f2tf(na1.y));
            as[6 * LD] = __uint_as_float(f2tf(na1.z));
            as[7 * LD] = __uint_as_float(f2tf(na1.w));
            float4 c0 = make_float4(__uint_as_float(f2tf(nb0.x)), __uint_as_float(f2tf(nb0.y)),
                                    __uint_as_float(f2tf(nb0.z)), __uint_as_float(f2tf(nb0.w)));
            float4 c1 = make_float4(__uint_as_float(f2tf(nb1.x)), __uint_as_float(f2tf(nb1.y)),
                                    __uint_as_float(f2tf(nb1.z)), __uint_as_float(f2tf(nb1.w)));
            *(float4*)&Bs[ns][brow][bcol]     = c0;
            *(float4*)&Bs[ns][brow][bcol + 4] = c1;
            __syncthreads();
            s = ns;
        }
    }

    // epilogue
#pragma unroll
    for (int mt = 0; mt < 4; mt++) {
#pragma unroll
        for (int half = 0; half < 2; half++) {
            int r = row0 + wrow + mt * 16 + g + half * 8;
#pragma unroll
            for (int nt = 0; nt < 4; nt++) {
                int c = col0 + wcol + nt * 8 + tq * 2;
                float v0 = C[mt][nt][half * 2 + 0] + bias[c];
                float v1 = C[mt][nt][half * 2 + 1] + bias[c + 1];
                if (EPI == 1) {
                    const float* rp = resid + (size_t)r * Nc + c;
                    v0 += rp[0]; v1 += rp[1];
                }
                if (EPI == 2) { v0 = fmaxf(v0, 0.f); v1 = fmaxf(v1, 0.f); }
                if (QKV) {
                    int b = r >> 9, n = r & 511, hh = c >> 6, dd = c & 63;
                    float* op = Cout + (((size_t)(b * NH + hh)) * SEQ + n) * HD + dd;
                    *(float2*)op = make_float2(v0, v1);
                } else {
                    *(float2*)(Cout + (size_t)r * Nc + c) = make_float2(v0, v1);
                }
            }
        }
    }
}

// ---------------- attention: streaming softmax, 8 q rows / CTA ------------
__global__ void attn_kernel(const int* __restrict__ lengths) {
    constexpr int QR = 8;
    int blk = blockIdx.x;
    int qt = blk % (SEQ / QR);
    int bh = blk / (SEQ / QR);
    int b = bh / NH, hh = bh % NH;
    int t = threadIdx.x;  // 64
    int w = t >> 5, lane = t & 31;

    __shared__ float k_sm[64][65];
    __shared__ float v_sm[64][65];
    __shared__ float q_sm[QR][64];
    __shared__ float p_sm[QR][64];
    __shared__ float red_max[16];
    __shared__ float red_sum[16];

    const float* Qp = g_q + ((size_t)bh * SEQ + qt * QR) * HD;
#pragma unroll
    for (int r = 0; r < QR; r++) q_sm[r][t] = Qp[r * HD + t] * 0.125f;

    float m[QR], l[QR], acc[QR];
#pragma unroll
    for (int r = 0; r < QR; r++) { m[r] = -1e30f; l[r] = 0.f; acc[r] = 0.f; }
    int len = lengths[b];

    const float* Kp = g_k + (size_t)bh * SEQ * HD;
    const float* Vp = g_v + (size_t)bh * SEQ * HD;

    for (int kt = 0; kt < SEQ; kt += 64) {
        __syncthreads();
#pragma unroll 4
        for (int rr = 0; rr < 64; rr++) {
            k_sm[rr][t] = Kp[(kt + rr) * HD + t];
            v_sm[rr][t] = Vp[(kt + rr) * HD + t];
        }
        __syncthreads();

        float s[QR];
#pragma unroll
        for (int r = 0; r < QR; r++) s[r] = 0.f;
#pragma unroll 8
        for (int d = 0; d < 64; d++) {
            float kv = k_sm[t][d];
#pragma unroll
            for (int r = 0; r < QR; r++) s[r] += q_sm[r][d] * kv;
        }
        if (kt + t >= len) {
#pragma unroll
            for (int r = 0; r < QR; r++) s[r] = -1e9f;
        }

#pragma unroll
        for (int r = 0; r < QR; r++) {
            float vm = s[r];
#pragma unroll
            for (int off = 16; off >= 1; off >>= 1)
                vm = fmaxf(vm, __shfl_xor_sync(0xffffffffu, vm, off));
            if (lane == 0) red_max[w * QR + r] = vm;
        }
        __syncthreads();

        float corr[QR];
#pragma unroll
        for (int r = 0; r < QR; r++) {
            float tmax = fmaxf(red_max[r], red_max[QR + r]);
            float mn = fmaxf(m[r], tmax);
            corr[r] = expf(m[r] - mn);
            m[r] = mn;
            float p = expf(s[r] - mn);
            p_sm[r][t] = p;
            float ps = p;
#pragma unroll
            for (int off = 16; off >= 1; off >>= 1)
                ps += __shfl_xor_sync(0xffffffffu, ps, off);
            if (lane == 0) red_sum[w * QR + r] = ps;
        }
        __syncthreads();

#pragma unroll
        for (int r = 0; r < QR; r++) {
            l[r] = l[r] * corr[r] + red_sum[r] + red_sum[QR + r];
            acc[r] *= corr[r];
        }
#pragma unroll 8
        for (int kk = 0; kk < 64; kk++) {
            float vv = v_sm[kk][t];
#pragma unroll
            for (int r = 0; r < QR; r++) acc[r] += p_sm[r][kk] * vv;
        }
    }

#pragma unroll
    for (int r = 0; r < QR; r++) {
        int qi = qt * QR + r;
        g_ctx[((size_t)b * SEQ + qi) * DIM + hh * HD + t] = acc[r] / l[r];
    }
}

// ---------------- outputs ----------------
__global__ void out1_kernel(float* __restrict__ out1) {
    int idx = blockIdx.x * blockDim.x + threadIdx.x;
    if (idx >= MR * DIM) return;
    int d = idx % DIM;
    int nb = idx / DIM;
    int b = nb % BATCH;
    int n = nb / BATCH;
    out1[idx] = g_h[((size_t)b * SEQ + n) * DIM + d];
}

__global__ void infw_kernel(const float* __restrict__ W) {
    int mrow = blockIdx.x;
    int t = threadIdx.x;  // 64
    float a[NCLS] = {0, 0, 0}, bv2[NCLS] = {0, 0, 0};
    const float* xp = g_h + (size_t)mrow * DIM;
    for (int d = t; d < DIM; d += 64) {
        float xv = xp[d];
#pragma unroll
        for (int c = 0; c < NCLS; c++) {
            a[c]   += xv * W[(size_t)d * NCLS + c];
            bv2[c] += xv * W[(size_t)(DIM + d) * NCLS + c];
        }
    }
    __shared__ float red[6][64];
#pragma unroll
    for (int c = 0; c < NCLS; c++) { red[c][t] = a[c]; red[3 + c][t] = bv2[c]; }
    __syncthreads();
    for (int sft = 32; sft >= 1; sft >>= 1) {
        if (t < sft) {
#pragma unroll
            for (int c = 0; c < 6; c++) red[c][t] += red[c][t + sft];
        }
        __syncthreads();
    }
    if (t == 0) {
#pragma unroll
        for (int c = 0; c < NCLS; c++) {
            g_la[mrow * NCLS + c] = red[c][0];
            g_lb[mrow * NCLS + c] = red[3 + c][0];
        }
    }
}

__global__ void pair_kernel(float* __restrict__ out2) {
    int idx = blockIdx.x * blockDim.x + threadIdx.x;
    if (idx >= SEQ * SEQ * BATCH) return;
    int b = idx % BATCH;
    int j = (idx / BATCH) % SEQ;
    int i = idx / (BATCH * SEQ);
    const float* lap = g_la + ((size_t)b * SEQ + i) * NCLS;
    const float* lbp = g_lb + ((size_t)b * SEQ + j) * NCLS;
    float v0 = lap[0] + lbp[0];
    float v1 = lap[1] + lbp[1];
    float v2 = lap[2] + lbp[2];
    float mx = fmaxf(v0, fmaxf(v1, v2));
    float lse = mx + logf(expf(v0 - mx) + expf(v1 - mx) + expf(v2 - mx));
    float* o = out2 + (size_t)idx * NCLS;
    o[0] = v0 - lse; o[1] = v1 - lse; o[2] = v2 - lse;
}

// ---------------- orchestration ----------------
extern "C" void kernel_launch(void* const* d_in, const int* in_sizes, int n_in,
                              void* d_out, int out_size) {
    (void)in_sizes; (void)n_in; (void)out_size;
    const int*   src     = (const int*)  d_in[0];
    const int*   lengths = (const int*)  d_in[1];
    const float* emb     = (const float*)d_in[2];
    const float* ln1_g   = (const float*)d_in[3];
    const float* ln1_b   = (const float*)d_in[4];
    const float* Wq      = (const float*)d_in[5];
    const float* bq      = (const float*)d_in[6];
    const float* Wk      = (const float*)d_in[7];
    const float* bk      = (const float*)d_in[8];
    const float* Wv      = (const float*)d_in[9];
    const float* bv      = (const float*)d_in[10];
    const float* Wo      = (const float*)d_in[11];
    const float* bo      = (const float*)d_in[12];
    const float* ln2_g   = (const float*)d_in[13];
    const float* ln2_b   = (const float*)d_in[14];
    const float* W1      = (const float*)d_in[15];
    const float* b1      = (const float*)d_in[16];
    const float* W2      = (const float*)d_in[17];
    const float* b2      = (const float*)d_in[18];
    const float* lnf_g   = (const float*)d_in[19];
    const float* lnf_b   = (const float*)d_in[20];
    const float* inf_W   = (const float*)d_in[21];
    float* out = (float*)d_out;

    float *px, *ph, *pq, *pk, *pv, *pctx, *pffn;
    cudaGetSymbolAddress((void**)&px,   g_x);
    cudaGetSymbolAddress((void**)&ph,   g_h);
    cudaGetSymbolAddress((void**)&pq,   g_q);
    cudaGetSymbolAddress((void**)&pk,   g_k);
    cudaGetSymbolAddress((void**)&pv,   g_v);
    cudaGetSymbolAddress((void**)&pctx, g_ctx);
    cudaGetSymbolAddress((void**)&pffn, g_ffn);

    embed_kernel<<<(MR * DIM + 255) / 256, 256>>>(src, emb);

    for (int l = 0; l < NL; l++) {
        const float* wq = Wq + (size_t)l * DIM * DIM;
        const float* wk = Wk + (size_t)l * DIM * DIM;
        const float* wv = Wv + (size_t)l * DIM * DIM;
        const float* wo = Wo + (size_t)l * DIM * DIM;
        const float* w1 = W1 + (size_t)l * DIM * DFFN;
        const float* w2 = W2 + (size_t)l * DFFN * DIM;

        ln_kernel<<<MR, 128>>>(px, ph, ln1_g + l * DIM, ln1_b + l * DIM);

        dim3 gD(DIM / 128, MR / 128);    // (4, 64)
        tgemm<0, 1><<<gD, 256>>>(ph, wq, bq + l * DIM, nullptr, pq, DIM, DIM);
        tgemm<0, 1><<<gD, 256>>>(ph, wk, bk + l * DIM, nullptr, pk, DIM, DIM);
        tgemm<0, 1><<<gD, 256>>>(ph, wv, bv + l * DIM, nullptr, pv, DIM, DIM);

        attn_kernel<<<BATCH * NH * SEQ / 8, 64>>>(lengths);

        tgemm<1, 0><<<gD, 256>>>(pctx, wo, bo + l * DIM, px, px, DIM, DIM);

        ln_kernel<<<MR, 128>>>(px, ph, ln2_g + l * DIM, ln2_b + l * DIM);

        dim3 gF(DFFN / 128, MR / 128);   // (16, 64)
        tgemm<2, 0><<<gF, 256>>>(ph, w1, b1 + l * DFFN, nullptr, pffn, DIM, DFFN);
        tgemm<1, 0><<<gD, 256>>>(pffn, w2, b2 + l * DIM, px, px, DFFN, DIM);
    }

    ln_kernel<<<MR, 128>>>(px, ph, lnf_g, lnf_b);

    out1_kernel<<<(MR * DIM + 255) / 256, 256>>>(out);
    infw_kernel<<<MR, 64>>>(inf_W);
    pair_kernel<<<(SEQ * SEQ * BATCH + 255) / 256, 256>>>(out + (size_t)MR * DIM);
}

// round 4
// speedup vs baseline: 3.1204x; 1.6395x over previous
#include <cuda_runtime.h>
#include <math.h>

constexpr int NL    = 4;
constexpr int DIM   = 512;
constexpr int NH    = 8;
constexpr int HD    = 64;
constexpr int DFFN  = 2048;
constexpr int SEQ   = 512;
constexpr int BATCH = 16;
constexpr int NCLS  = 3;
constexpr int MR    = BATCH * SEQ;  // 8192
constexpr int NBH   = BATCH * NH;   // 128

// ---------------- scratch ----------------
__device__ float g_x  [MR * DIM];
__device__ float g_h  [MR * DIM];
__device__ float g_q  [MR * DIM];   // [B,H,N,HD]
__device__ float g_k  [MR * DIM];   // [B,H,HD,N] (transposed)
__device__ float g_v  [MR * DIM];   // [B,H,N,HD]
__device__ float g_ctx[MR * DIM];
__device__ float g_ffn[MR * DFFN];
__device__ float g_sc [(size_t)NBH * SEQ * SEQ];  // attention scores [B*H,N,N] (134 MB)
__device__ float g_la [MR * NCLS];
__device__ float g_lb [MR * NCLS];

// ---------------- embedding + PE ----------------
__global__ void embed_kernel(const int* __restrict__ src,
                             const float* __restrict__ emb) {
    int idx = blockIdx.x * blockDim.x + threadIdx.x;
    if (idx >= MR * DIM) return;
    int d = idx % DIM;
    int m = idx / DIM;
    int b = m / SEQ;
    int n = m % SEQ;
    int tok = src[n * BATCH + b];
    float e = emb[(size_t)tok * DIM + d] * 22.62741699796952f;
    int i2 = (d >> 1) * 2;
    float freq = expf((float)i2 * (-9.210340371976184f / (float)DIM));
    float ang = (float)n * freq;
    float pe = (d & 1) ? cosf(ang) : sinf(ang);
    g_x[idx] = e + pe;
}

// ---------------- LayerNorm ----------------
__global__ void ln_kernel(const float* __restrict__ in, float* __restrict__ out,
                          const float* __restrict__ gg, const float* __restrict__ bb) {
    int row = blockIdx.x;
    int t = threadIdx.x;
    const float* p = in + (size_t)row * DIM;
    float v[4];
    float s = 0.f, ss = 0.f;
#pragma unroll
    for (int i = 0; i < 4; i++) {
        float x = p[t + i * 128];
        v[i] = x; s += x; ss += x * x;
    }
#pragma unroll
    for (int off = 16; off >= 1; off >>= 1) {
        s  += __shfl_xor_sync(0xffffffffu, s, off);
        ss += __shfl_xor_sync(0xffffffffu, ss, off);
    }
    __shared__ float rs[4], rss[4];
    int w = t >> 5, lane = t & 31;
    if (lane == 0) { rs[w] = s; rss[w] = ss; }
    __syncthreads();
    float S  = rs[0] + rs[1] + rs[2] + rs[3];
    float SS = rss[0] + rss[1] + rss[2] + rss[3];
    float mean = S * (1.f / DIM);
    float var  = SS * (1.f / DIM) - mean * mean;
    float rstd = rsqrtf(var + 1e-6f);
    float* o = out + (size_t)row * DIM;
#pragma unroll
    for (int i = 0; i < 4; i++) {
        int c = t + i * 128;
        o[c] = (v[i] - mean) * rstd * gg[c] + bb[c];
    }
}

// ---------------- tf32 helpers ----------------
__device__ __forceinline__ float f2tf_f(float x) {
    unsigned r;
    asm("cvt.rna.tf32.f32 %0, %1;" : "=r"(r) : "f"(x));
    return __uint_as_float(r);
}

__device__ __forceinline__ void mma_tf32(float c[4], const unsigned a[4], const unsigned b[2]) {
    asm volatile(
        "mma.sync.aligned.m16n8k8.row.col.f32.tf32.tf32.f32 "
        "{%0,%1,%2,%3}, {%4,%5,%6,%7}, {%8,%9}, {%0,%1,%2,%3};"
        : "+f"(c[0]), "+f"(c[1]), "+f"(c[2]), "+f"(c[3])
        : "r"(a[0]), "r"(a[1]), "r"(a[2]), "r"(a[3]),
          "r"(b[0]), "r"(b[1]));
}

// ---------------- generalized tensor-core GEMM (tf32) ----------------
// C[z][M,N] = A[z][M,K] @ W[z][K,N]. BM fixed 128, 256 threads (8 warps).
// BN in {128, 64}; WM in {64, 32} with warp tile WM x 32.
// EPI: 0 = bias, 1 = bias + residual, 2 = bias + relu, 3 = raw
// SCAT: 0 = plain, 1 = QKV scatter [B,H,N,HD], 2 = K^T scatter [B,H,HD,N],
//       3 = ctx scatter (batched over bh): ctx[(b*SEQ+q)*DIM + h*HD + c]
template<int BN, int WM, int EPI, int SCAT>
__global__ __launch_bounds__(256, 2)
void tgemm(const float* __restrict__ A, const float* __restrict__ W,
           const float* __restrict__ bias, const float* __restrict__ resid,
           float* __restrict__ Cout, int K, int lda, int ldb, int ldc,
           long long sA, long long sB, long long sC) {
    constexpr int BK  = 16;
    constexpr int LDA = 136;
    constexpr int LDB = BN + 8;
    constexpr int NWM = 128 / WM;
    constexpr int MT  = WM / 16;
    constexpr int BNF = BN / 16;

    __shared__ float As[2][BK][LDA];
    __shared__ float Bs[2][BK][LDB];

    const int tid  = threadIdx.x;
    const int w    = tid >> 5;
    const int lane = tid & 31;
    const int g    = lane >> 2;
    const int tq   = lane & 3;
    const int wrow = (w % NWM) * WM;
    const int wcol = (w / NWM) * 32;
    const int z    = blockIdx.z;
    const int row0 = blockIdx.y * 128;
    const int col0 = blockIdx.x * BN;

    A += (size_t)z * sA;
    W += (size_t)z * sB;

    const int arow = tid >> 1;
    const int acol = (tid & 1) * 8;
    const int brow = tid >> 4;
    const int bcol = (tid & 15) * BNF;

    const float* Ap = A + (size_t)(row0 + arow) * lda + acol;
    const float* Wp = W + (size_t)brow * ldb + col0 + bcol;

    float C[MT][4][4];
#pragma unroll
    for (int i = 0; i < MT; i++)
#pragma unroll
        for (int j = 0; j < 4; j++)
#pragma unroll
            for (int q = 0; q < 4; q++) C[i][j][q] = 0.f;

    const int nblk = K / BK;

    float ar[8], br[BNF];
#pragma unroll
    for (int i = 0; i < 2; i++) *(float4*)(ar + i * 4) = *(const float4*)(Ap + i * 4);
#pragma unroll
    for (int i = 0; i < BNF / 4; i++) *(float4*)(br + i * 4) = *(const float4*)(Wp + i * 4);

    {
        float* as = &As[0][acol][arow];
#pragma unroll
        for (int i = 0; i < 8; i++) as[i * LDA] = f2tf_f(ar[i]);
        float* bs = &Bs[0][brow][bcol];
#pragma unroll
        for (int i = 0; i < BNF; i++) bs[i] = f2tf_f(br[i]);
    }
    __syncthreads();

    int s = 0;
    for (int blk = 0; blk < nblk; blk++) {
        if (blk + 1 < nblk) {
            const float* ap = Ap + (blk + 1) * BK;
            const float* wp = Wp + (size_t)(blk + 1) * BK * ldb;
#pragma unroll
            for (int i = 0; i < 2; i++) *(float4*)(ar + i * 4) = *(const float4*)(ap + i * 4);
#pragma unroll
            for (int i = 0; i < BNF / 4; i++) *(float4*)(br + i * 4) = *(const float4*)(wp + i * 4);
        }

#pragma unroll
        for (int ks = 0; ks < 2; ks++) {
            const int kb = ks * 8;
            unsigned af[MT][4], bf[4][2];
#pragma unroll
            for (int mt = 0; mt < MT; mt++) {
                int r = wrow + mt * 16 + g;
                af[mt][0] = __float_as_uint(As[s][kb + tq][r]);
                af[mt][1] = __float_as_uint(As[s][kb + tq][r + 8]);
                af[mt][2] = __float_as_uint(As[s][kb + tq + 4][r]);
                af[mt][3] = __float_as_uint(As[s][kb + tq + 4][r + 8]);
            }
#pragma unroll
            for (int nt = 0; nt < 4; nt++) {
                int c = wcol + nt * 8 + g;
                bf[nt][0] = __float_as_uint(Bs[s][kb + tq][c]);
                bf[nt][1] = __float_as_uint(Bs[s][kb + tq + 4][c]);
            }
#pragma unroll
            for (int mt = 0; mt < MT; mt++)
#pragma unroll
                for (int nt = 0; nt < 4; nt++)
                    mma_tf32(C[mt][nt], af[mt], bf[nt]);
        }

        if (blk + 1 < nblk) {
            int ns = s ^ 1;
            float* as = &As[ns][acol][arow];
#pragma unroll
            for (int i = 0; i < 8; i++) as[i * LDA] = f2tf_f(ar[i]);
            float* bs = &Bs[ns][brow][bcol];
#pragma unroll
            for (int i = 0; i < BNF; i++) bs[i] = f2tf_f(br[i]);
            __syncthreads();
            s = ns;
        }
    }

    // epilogue
#pragma unroll
    for (int mt = 0; mt < MT; mt++) {
#pragma unroll
        for (int half = 0; half < 2; half++) {
            int r = row0 + wrow + mt * 16 + g + half * 8;
#pragma unroll
            for (int nt = 0; nt < 4; nt++) {
                int c = col0 + wcol + nt * 8 + tq * 2;
                float v0 = C[mt][nt][half * 2 + 0];
                float v1 = C[mt][nt][half * 2 + 1];
                if (EPI != 3) { v0 += bias[c]; v1 += bias[c + 1]; }
                if (EPI == 1) {
                    const float* rp = resid + (size_t)r * ldc + c;
                    v0 += rp[0]; v1 += rp[1];
                }
                if (EPI == 2) { v0 = fmaxf(v0, 0.f); v1 = fmaxf(v1, 0.f); }
                if (SCAT == 1) {
                    int b = r >> 9, n = r & 511, hh = c >> 6, dd = c & 63;
                    float* op = Cout + (((size_t)(b * NH + hh)) * SEQ + n) * HD + dd;
                    *(float2*)op = make_float2(v0, v1);
                } else if (SCAT == 2) {
                    int b = r >> 9, n = r & 511, hh = c >> 6, dd = c & 63;
                    float* op = Cout + ((size_t)(b * NH + hh) * HD + dd) * SEQ + n;
                    op[0] = v0;
                    op[SEQ] = v1;
                } else if (SCAT == 3) {
                    int b = z >> 3, hh = z & 7;
                    float* op = Cout + ((size_t)(b * SEQ + r)) * DIM + hh * HD + c;
                    *(float2*)op = make_float2(v0, v1);
                } else {
                    *(float2*)(Cout + (size_t)z * sC + (size_t)r * ldc + c) =
                        make_float2(v0, v1);
                }
            }
        }
    }
}

// ---------------- masked softmax over scores rows (in place) --------------
// S layout [B*H, N, N]; row = bh*SEQ + q; scale 1/sqrt(HD) folded here.
__global__ void softmax_kernel(float* __restrict__ S, const int* __restrict__ lengths) {
    int row = blockIdx.x;
    int b = row >> 12;                 // row / (NH*SEQ)
    int t = threadIdx.x;               // 128
    float* p = S + (size_t)row * SEQ;
    int len = lengths[b];

    float v[4];
    float mx = -1e30f;
#pragma unroll
    for (int i = 0; i < 4; i++) {
        int c = t + i * 128;
        float x = p[c] * 0.125f;
        if (c >= len) x = -1e30f;
        v[i] = x;
        mx = fmaxf(mx, x);
    }
#pragma unroll
    for (int off = 16; off >= 1; off >>= 1)
        mx = fmaxf(mx, __shfl_xor_sync(0xffffffffu, mx, off));
    __shared__ float rm[4], rsum[4];
    int w = t >> 5, lane = t & 31;
    if (lane == 0) rm[w] = mx;
    __syncthreads();
    float M = fmaxf(fmaxf(rm[0], rm[1]), fmaxf(rm[2], rm[3]));

    float sum = 0.f;
#pragma unroll
    for (int i = 0; i < 4; i++) {
        float e = expf(v[i] - M);
        v[i] = e;
        sum += e;
    }
#pragma unroll
    for (int off = 16; off >= 1; off >>= 1)
        sum += __shfl_xor_sync(0xffffffffu, sum, off);
    if (lane == 0) rsum[w] = sum;
    __syncthreads();
    float inv = 1.f / (rsum[0] + rsum[1] + rsum[2] + rsum[3]);
#pragma unroll
    for (int i = 0; i < 4; i++) p[t + i * 128] = v[i] * inv;
}

// ---------------- outputs ----------------
__global__ void out1_kernel(float* __restrict__ out1) {
    int idx = blockIdx.x * blockDim.x + threadIdx.x;
    if (idx >= MR * DIM) return;
    int d = idx % DIM;
    int nb = idx / DIM;
    int b = nb % BATCH;
    int n = nb / BATCH;
    out1[idx] = g_h[((size_t)b * SEQ + n) * DIM + d];
}

__global__ void infw_kernel(const float* __restrict__ W) {
    int mrow = blockIdx.x;
    int t = threadIdx.x;  // 64
    float a[NCLS] = {0, 0, 0}, bv2[NCLS] = {0, 0, 0};
    const float* xp = g_h + (size_t)mrow * DIM;
    for (int d = t; d < DIM; d += 64) {
        float xv = xp[d];
#pragma unroll
        for (int c = 0; c < NCLS; c++) {
            a[c]   += xv * W[(size_t)d * NCLS + c];
            bv2[c] += xv * W[(size_t)(DIM + d) * NCLS + c];
        }
    }
    __shared__ float red[6][64];
#pragma unroll
    for (int c = 0; c < NCLS; c++) { red[c][t] = a[c]; red[3 + c][t] = bv2[c]; }
    __syncthreads();
    for (int sft = 32; sft >= 1; sft >>= 1) {
        if (t < sft) {
#pragma unroll
            for (int c = 0; c < 6; c++) red[c][t] += red[c][t + sft];
        }
        __syncthreads();
    }
    if (t == 0) {
#pragma unroll
        for (int c = 0; c < NCLS; c++) {
            g_la[mrow * NCLS + c] = red[c][0];
            g_lb[mrow * NCLS + c] = red[3 + c][0];
        }
    }
}

__global__ void pair_kernel(float* __restrict__ out2) {
    int idx = blockIdx.x * blockDim.x + threadIdx.x;
    if (idx >= SEQ * SEQ * BATCH) return;
    int b = idx % BATCH;
    int j = (idx / BATCH) % SEQ;
    int i = idx / (BATCH * SEQ);
    const float* lap = g_la + ((size_t)b * SEQ + i) * NCLS;
    const float* lbp = g_lb + ((size_t)b * SEQ + j) * NCLS;
    float v0 = lap[0] + lbp[0];
    float v1 = lap[1] + lbp[1];
    float v2 = lap[2] + lbp[2];
    float mx = fmaxf(v0, fmaxf(v1, v2));
    float lse = mx + logf(expf(v0 - mx) + expf(v1 - mx) + expf(v2 - mx));
    float* o = out2 + (size_t)idx * NCLS;
    o[0] = v0 - lse; o[1] = v1 - lse; o[2] = v2 - lse;
}

// ---------------- orchestration ----------------
extern "C" void kernel_launch(void* const* d_in, const int* in_sizes, int n_in,
                              void* d_out, int out_size) {
    (void)in_sizes; (void)n_in; (void)out_size;
    const int*   src     = (const int*)  d_in[0];
    const int*   lengths = (const int*)  d_in[1];
    const float* emb     = (const float*)d_in[2];
    const float* ln1_g   = (const float*)d_in[3];
    const float* ln1_b   = (const float*)d_in[4];
    const float* Wq      = (const float*)d_in[5];
    const float* bq      = (const float*)d_in[6];
    const float* Wk      = (const float*)d_in[7];
    const float* bk      = (const float*)d_in[8];
    const float* Wv      = (const float*)d_in[9];
    const float* bv      = (const float*)d_in[10];
    const float* Wo      = (const float*)d_in[11];
    const float* bo      = (const float*)d_in[12];
    const float* ln2_g   = (const float*)d_in[13];
    const float* ln2_b   = (const float*)d_in[14];
    const float* W1      = (const float*)d_in[15];
    const float* b1      = (const float*)d_in[16];
    const float* W2      = (const float*)d_in[17];
    const float* b2      = (const float*)d_in[18];
    const float* lnf_g   = (const float*)d_in[19];
    const float* lnf_b   = (const float*)d_in[20];
    const float* inf_W   = (const float*)d_in[21];
    float* out = (float*)d_out;

    float *px, *ph, *pq, *pk, *pv, *pctx, *pffn, *psc;
    cudaGetSymbolAddress((void**)&px,   g_x);
    cudaGetSymbolAddress((void**)&ph,   g_h);
    cudaGetSymbolAddress((void**)&pq,   g_q);
    cudaGetSymbolAddress((void**)&pk,   g_k);
    cudaGetSymbolAddress((void**)&pv,   g_v);
    cudaGetSymbolAddress((void**)&pctx, g_ctx);
    cudaGetSymbolAddress((void**)&pffn, g_ffn);
    cudaGetSymbolAddress((void**)&psc,  g_sc);

    embed_kernel<<<(MR * DIM + 255) / 256, 256>>>(src, emb);

    const long long sBH = (long long)SEQ * HD;      // 32768
    const long long sSC = (long long)SEQ * SEQ;     // 262144

    for (int l = 0; l < NL; l++) {
        const float* wq = Wq + (size_t)l * DIM * DIM;
        const float* wk = Wk + (size_t)l * DIM * DIM;
        const float* wv = Wv + (size_t)l * DIM * DIM;
        const float* wo = Wo + (size_t)l * DIM * DIM;
        const float* w1 = W1 + (size_t)l * DIM * DFFN;
        const float* w2 = W2 + (size_t)l * DFFN * DIM;

        ln_kernel<<<MR, 128>>>(px, ph, ln1_g + l * DIM, ln1_b + l * DIM);

        dim3 gD(DIM / 128, MR / 128, 1);    // (4, 64)
        tgemm<128, 64, 0, 1><<<gD, 256>>>(ph, wq, bq + l * DIM, nullptr, pq,
                                          DIM, DIM, DIM, DIM, 0, 0, 0);
        tgemm<128, 64, 0, 2><<<gD, 256>>>(ph, wk, bk + l * DIM, nullptr, pk,
                                          DIM, DIM, DIM, DIM, 0, 0, 0);
        tgemm<128, 64, 0, 1><<<gD, 256>>>(ph, wv, bv + l * DIM, nullptr, pv,
                                          DIM, DIM, DIM, DIM, 0, 0, 0);

        // scores = Q @ K^T  (batched over B*H=128)
        dim3 gS(SEQ / 128, SEQ / 128, NBH);  // (4, 4, 128)
        tgemm<128, 64, 3, 0><<<gS, 256>>>(pq, pk, nullptr, nullptr, psc,
                                          HD, HD, SEQ, SEQ, sBH, sBH, sSC);

        softmax_kernel<<<NBH * SEQ, 128>>>(psc, lengths);

        // ctx = P @ V  (batched over B*H), scatter into [B,N,D]
        dim3 gP(1, SEQ / 128, NBH);          // (1, 4, 128)
        tgemm<64, 32, 3, 3><<<gP, 256>>>(psc, pv, nullptr, nullptr, pctx,
                                         SEQ, SEQ, HD, 0, sSC, sBH, 0);

        tgemm<128, 64, 1, 0><<<gD, 256>>>(pctx, wo, bo + l * DIM, px, px,
                                          DIM, DIM, DIM, DIM, 0, 0, 0);

        ln_kernel<<<MR, 128>>>(px, ph, ln2_g + l * DIM, ln2_b + l * DIM);

        dim3 gF(DFFN / 128, MR / 128, 1);   // (16, 64)
        tgemm<128, 64, 2, 0><<<gF, 256>>>(ph, w1, b1 + l * DFFN, nullptr, pffn,
                                          DIM, DIM, DFFN, DFFN, 0, 0, 0);
        tgemm<128, 64, 1, 0><<<gD, 256>>>(pffn, w2, b2 + l * DIM, px, px,
                                          DFFN, DFFN, DIM, DIM, 0, 0, 0);
    }

    ln_kernel<<<MR, 128>>>(px, ph, lnf_g, lnf_b);

    out1_kernel<<<(MR * DIM + 255) / 256, 256>>>(out);
    infw_kernel<<<MR, 64>>>(inf_W);
    pair_kernel<<<(SEQ * SEQ * BATCH + 255) / 256, 256>>>(out + (size_t)MR * DIM);
}